// round 12
// baseline (speedup 1.0000x reference)
#include <cuda_runtime.h>
#include <cuda_fp16.h>
#include <cstdint>

// ----------------------------------------------------------------------------
// Packed bidirectional 2-layer LSTM.
//   inputs : input(total,256) f32, batch_sizes(T) i32, h0(4,64,128), c0(4,64,128),
//            W_ih(4,512,256), W_hh(4,512,128), b_ih(4,512), b_hh(4,512)
//   outputs: packed_out(total,256) | h_n(4,64,128) | c_n(4,64,128)
// ----------------------------------------------------------------------------

#define TOTAL_MAX 49408
#define TMAX      1024
#define AK        72            // padded smem stride in halves (144B, conflict-free)

__device__ float  g_gpre[2 * TOTAL_MAX * 512];
__device__ __half g_A16 [TOTAL_MAX * 256];      // layer-0 input, fp16
__device__ __half g_out1h[TOTAL_MAX * 256];     // layer-1 input (rec-l0 output), fp16
__device__ __half g_W16 [4 * 512 * 256];        // W_ih in fp16
__device__ int    g_offsets[TMAX];
__device__ int    g_len[64];

typedef unsigned long long ull;

__device__ __forceinline__ __half2 uh2(unsigned int u)
{
    return *reinterpret_cast<__half2*>(&u);
}
__device__ __forceinline__ unsigned int h2u(__half2 h)
{
    return *reinterpret_cast<unsigned int*>(&h);
}

// ---- HMMA building blocks ----
__device__ __forceinline__ void cp16(uint32_t saddr, const void* gptr)
{
    asm volatile("cp.async.cg.shared.global [%0], [%1], 16;"
                 :: "r"(saddr), "l"(gptr) : "memory");
}
__device__ __forceinline__ void ldsm_x4(uint32_t& r0, uint32_t& r1,
                                        uint32_t& r2, uint32_t& r3, uint32_t addr)
{
    asm volatile("ldmatrix.sync.aligned.m8n8.x4.shared.b16 {%0,%1,%2,%3}, [%4];"
                 : "=r"(r0), "=r"(r1), "=r"(r2), "=r"(r3) : "r"(addr));
}
__device__ __forceinline__ void ldsm_x2(uint32_t& r0, uint32_t& r1, uint32_t addr)
{
    asm volatile("ldmatrix.sync.aligned.m8n8.x2.shared.b16 {%0,%1}, [%2];"
                 : "=r"(r0), "=r"(r1) : "r"(addr));
}
__device__ __forceinline__ void mma16816(float* c,
                                         uint32_t a0, uint32_t a1, uint32_t a2, uint32_t a3,
                                         uint32_t b0, uint32_t b1)
{
    asm volatile("mma.sync.aligned.m16n8k16.row.col.f32.f16.f16.f32 "
                 "{%0,%1,%2,%3}, {%4,%5,%6,%7}, {%8,%9}, {%0,%1,%2,%3};"
                 : "+f"(c[0]), "+f"(c[1]), "+f"(c[2]), "+f"(c[3])
                 : "r"(a0), "r"(a1), "r"(a2), "r"(a3), "r"(b0), "r"(b1));
}

// ---------------------------------------------------------------- setup -----
__global__ void setup_kernel(const int* __restrict__ bs, int T)
{
    __shared__ int s[TMAX];
    int tid = threadIdx.x;
    if (tid < T) s[tid] = bs[tid];
    __syncthreads();
    if (tid == 0) {
        int off = 0;
        for (int t = 0; t < T; ++t) { g_offsets[t] = off; off += s[t]; }
    }
    if (tid < 64) {
        int c = 0;
        for (int t = 0; t < T; ++t) c += (s[t] > tid) ? 1 : 0;
        g_len[tid] = c;
    }
}

// f32 -> f16 bulk convert, both arrays in ONE launch (keeps launch count at 6
// so ncu -s 5 -c 1 captures the layer-1 rec_kernel).
__global__ void cvt_kernel(const float* __restrict__ srcA, __half* __restrict__ dstA, int n4a,
                           const float* __restrict__ srcW, __half* __restrict__ dstW, int n4w)
{
    int i = blockIdx.x * blockDim.x + threadIdx.x;
    const float* src;
    __half* dst;
    int j;
    if (i < n4a) { src = srcA; dst = dstA; j = i; }
    else if (i < n4a + n4w) { src = srcW; dst = dstW; j = i - n4a; }
    else return;
    float4 v = reinterpret_cast<const float4*>(src)[j];
    __half2 lo = __floats2half2_rn(v.x, v.y);
    __half2 hi = __floats2half2_rn(v.z, v.w);
    uint2 u;
    u.x = h2u(lo);
    u.y = h2u(hi);
    reinterpret_cast<uint2*>(dst)[j] = u;
}

// ------------------------------------------------------------ HMMA gemm -----
// gpre[dir][tok][g] = A16[tok][:] . W16[layer][dir*512+g][:] + bias
// CTA tile 128(m) x 128(n). K=256 in 4 stages of 64, double-buffered cp.async.
// 8 warps: warpM(2) x warpN(4); warp tile 64x32; mma.m16n8k16 f16 -> f32.
__global__ __launch_bounds__(256, 2)
void gemm_hmma(const __half* __restrict__ Ah,
               const float* __restrict__ bih_all,
               const float* __restrict__ bhh_all,
               int total, int layer)
{
    extern __shared__ __half shbuf[];
    const int STAGE = 2 * 128 * AK;                 // halves per stage (A + B tiles)
    const uint32_t sbase = (uint32_t)__cvta_generic_to_shared(shbuf);

    const __half* Wl = g_W16 + (size_t)layer * 262144;
    const float*  bi = bih_all + layer * 1024;
    const float*  bh = bhh_all + layer * 1024;

    const int tid   = threadIdx.x;
    const int lane  = tid & 31;
    const int wid   = tid >> 5;
    const int warpM = wid >> 2;                     // 0..1
    const int warpN = wid & 3;                      // 0..3
    const int mBase = blockIdx.x * 128;
    const int nBase = blockIdx.y * 128;

    const int r0 = tid >> 3;                        // cp.async row (0..31)
    const int c0 = tid & 7;                         // 16B chunk (0..7)

    const int grp  = lane >> 3;
    const int rinl = lane & 7;
    const int aRow = warpM * 64 + (grp & 1) * 8 + rinl;
    const int aCol = (grp >> 1) * 8;
    const int bRowBase = warpN * 32 + rinl;
    const int bCol = ((lane >> 3) & 1) * 8;

    float acc[4][4][4];
#pragma unroll
    for (int i = 0; i < 4; ++i)
#pragma unroll
        for (int j = 0; j < 4; ++j)
#pragma unroll
            for (int v = 0; v < 4; ++v) acc[i][j][v] = 0.f;

    // ---- prologue: stage 0 into buffer 0
#pragma unroll
    for (int i = 0; i < 4; ++i) {
        int r = r0 + i * 32;
        int arow = mBase + r;
        if (arow > total - 1) arow = total - 1;
        cp16(sbase + (uint32_t)(r * AK + c0 * 8) * 2,
             Ah + (size_t)arow * 256 + c0 * 8);
        cp16(sbase + (uint32_t)(128 * AK + r * AK + c0 * 8) * 2,
             Wl + (size_t)(nBase + r) * 256 + c0 * 8);
    }
    asm volatile("cp.async.commit_group;" ::: "memory");

    for (int s = 0; s < 4; ++s) {
        if (s < 3) {
            const int ks  = s + 1;
            const int nbf = ks & 1;
#pragma unroll
            for (int i = 0; i < 4; ++i) {
                int r = r0 + i * 32;
                int arow = mBase + r;
                if (arow > total - 1) arow = total - 1;
                cp16(sbase + (uint32_t)(nbf * STAGE + r * AK + c0 * 8) * 2,
                     Ah + (size_t)arow * 256 + ks * 64 + c0 * 8);
                cp16(sbase + (uint32_t)(nbf * STAGE + 128 * AK + r * AK + c0 * 8) * 2,
                     Wl + (size_t)(nBase + r) * 256 + ks * 64 + c0 * 8);
            }
        }
        asm volatile("cp.async.commit_group;" ::: "memory");
        if (s < 3) asm volatile("cp.async.wait_group 1;" ::: "memory");
        else       asm volatile("cp.async.wait_group 0;" ::: "memory");
        __syncthreads();

        const int buf = s & 1;
        const uint32_t aTile = sbase + (uint32_t)(buf * STAGE) * 2;
        const uint32_t bTile = sbase + (uint32_t)(buf * STAGE + 128 * AK) * 2;

#pragma unroll
        for (int kk = 0; kk < 4; ++kk) {
            uint32_t af[4][4];
            uint32_t bf[4][2];
#pragma unroll
            for (int mf = 0; mf < 4; ++mf) {
                uint32_t aaddr = aTile +
                    (uint32_t)((aRow + mf * 16) * AK + kk * 16 + aCol) * 2;
                ldsm_x4(af[mf][0], af[mf][1], af[mf][2], af[mf][3], aaddr);
            }
#pragma unroll
            for (int nf = 0; nf < 4; ++nf) {
                uint32_t baddr = bTile +
                    (uint32_t)((bRowBase + nf * 8) * AK + kk * 16 + bCol) * 2;
                ldsm_x2(bf[nf][0], bf[nf][1], baddr);
            }
#pragma unroll
            for (int mf = 0; mf < 4; ++mf)
#pragma unroll
                for (int nf = 0; nf < 4; ++nf)
                    mma16816(acc[mf][nf],
                             af[mf][0], af[mf][1], af[mf][2], af[mf][3],
                             bf[nf][0], bf[nf][1]);
        }
        __syncthreads();
    }

    // ---- epilogue: bias add + scatter to g_gpre[dir][tok][g]
    const int mW = mBase + warpM * 64 + (lane >> 2);
    const int nW = nBase + warpN * 32 + ((lane & 3) << 1);
#pragma unroll
    for (int nf = 0; nf < 4; ++nf) {
        int n = nW + nf * 8;
        float bias0 = bi[n] + bh[n];
        float bias1 = bi[n + 1] + bh[n + 1];
        int dirr = n >> 9;
        int g    = n & 511;
        float* gp = g_gpre + (size_t)dirr * (size_t)total * 512 + g;
#pragma unroll
        for (int mf = 0; mf < 4; ++mf) {
            int m0 = mW + mf * 16;
            if (m0 < total) {
                float2 v = make_float2(acc[mf][nf][0] + bias0, acc[mf][nf][1] + bias1);
                *reinterpret_cast<float2*>(gp + (size_t)m0 * 512) = v;
            }
            int m1 = m0 + 8;
            if (m1 < total) {
                float2 v = make_float2(acc[mf][nf][2] + bias0, acc[mf][nf][3] + bias1);
                *reinterpret_cast<float2*>(gp + (size_t)m1 * 512) = v;
            }
        }
    }
}

// ------------------------------------------------------------- recurrence ---
// HW tanh: single MUFU op (sm_75+).
__device__ __forceinline__ float tanha(float x)
{
    float y;
    asm("tanh.approx.f32 %0, %1;" : "=f"(y) : "f"(x));
    return y;
}
__device__ __forceinline__ float sigf(float x)
{
    return fmaf(tanha(0.5f * x), 0.5f, 0.5f);
}

// 128 CTAs: blockIdx.x = dir*64 + b. 256 threads, 2 gates/thread (tid, tid+256).
// All W_hh in fp16 registers (128 u32). h in fp16 SMEM, 16 uint4 broadcast
// loads shared by both gates. Activations applied in the PARALLEL phase
// (thread's own gates), so the serial gate phase is just the c/h update.
// gpre prefetched 2 steps ahead (covers bursty DRAM latency).
__global__ __launch_bounds__(256, 1)
void rec_kernel(const float* __restrict__ Whh_all,
                const float* __restrict__ h0,
                const float* __restrict__ c0,
                float* __restrict__ dout,
                int total, int T, int layer)
{
    __shared__ __align__(16) float  hs[128];
    __shared__ __align__(16) __half hsh[128];
    __shared__ __align__(16) float  zs[512];   // zs[2t] = (act(z_t), act(z_{t+256}))
    __shared__ int   offs[TMAX];

    const int tid = threadIdx.x;
    const int dir = blockIdx.x >> 6;
    const int b   = blockIdx.x & 63;
    const int kix = 2 * layer + dir;

    const float* gpd = g_gpre + (size_t)dir * (size_t)total * 512;
    const float* W   = Whh_all + (size_t)kix * 512 * 128;

    for (int i = tid; i < T; i += 256) offs[i] = g_offsets[i];

    // all K=128 weights for both gates in fp16 half2 registers
    unsigned int whr[2][64];
#pragma unroll
    for (int e = 0; e < 2; ++e) {
        const float* wg = &W[(tid + 256 * e) * 128];
#pragma unroll
        for (int c = 0; c < 16; ++c) {
            float4 w0 = *reinterpret_cast<const float4*>(&wg[c * 8]);
            float4 w1 = *reinterpret_cast<const float4*>(&wg[c * 8 + 4]);
            whr[e][c * 4 + 0] = h2u(__floats2half2_rn(w0.x, w0.y));
            whr[e][c * 4 + 1] = h2u(__floats2half2_rn(w0.z, w0.w));
            whr[e][c * 4 + 2] = h2u(__floats2half2_rn(w1.x, w1.y));
            whr[e][c * 4 + 3] = h2u(__floats2half2_rn(w1.z, w1.w));
        }
    }

    float creg = 0.f;
    if (tid < 128) {
        float hv = h0[(size_t)kix * 8192 + b * 128 + tid];
        hs[tid]  = hv;
        hsh[tid] = __float2half_rn(hv);
        creg = c0[(size_t)kix * 8192 + b * 128 + tid];
    }
    __syncthreads();

    const int  len = g_len[b];
    const bool fwd = (dir == 0);

    // ---- gpre prefetch pipeline, depth 2
    int   tokb[2];
    float g0b[2], g1b[2];
    tokb[0] = offs[fwd ? 0 : (len - 1)] + b;
    g0b[0] = gpd[(size_t)tokb[0] * 512 + tid];
    g1b[0] = gpd[(size_t)tokb[0] * 512 + tid + 256];
    tokb[1] = 0; g0b[1] = 0.f; g1b[1] = 0.f;
    if (len > 1) {
        int t1 = fwd ? 1 : (len - 2);
        tokb[1] = offs[t1] + b;
        g0b[1] = gpd[(size_t)tokb[1] * 512 + tid];
        g1b[1] = gpd[(size_t)tokb[1] * 512 + tid + 256];
    }

    const uint4*  hhp = reinterpret_cast<const uint4*>(hsh);
    const __half2 hzero = __floats2half2_rn(0.f, 0.f);
    const bool loGroup = (tid < 128);               // warp-uniform

    for (int s = 0; s < len; ++s) {
        const int cur = s & 1;
        const int   tok   = tokb[cur];
        const float gcur0 = g0b[cur];
        const float gcur1 = g1b[cur];

        // prefetch step s+2
        int   toknew = 0;
        float gnew0 = 0.f, gnew1 = 0.f;
        if (s + 2 < len) {
            int tn = fwd ? (s + 2) : (len - 3 - s);
            toknew = offs[tn] + b;
            gnew0  = gpd[(size_t)toknew * 512 + tid];
            gnew1  = gpd[(size_t)toknew * 512 + tid + 256];
        }

        // dot products: 16 shared h loads, 8 chains (depth 8) per gate
        __half2 a0[8], a1[8];
#pragma unroll
        for (int j = 0; j < 8; ++j) { a0[j] = hzero; a1[j] = hzero; }
#pragma unroll
        for (int c = 0; c < 16; ++c) {
            uint4 hv = hhp[c];                      // broadcast LDS.128
            const int base = (c & 1) * 4;
            a0[base + 0] = __hfma2(uh2(whr[0][c * 4 + 0]), uh2(hv.x), a0[base + 0]);
            a0[base + 1] = __hfma2(uh2(whr[0][c * 4 + 1]), uh2(hv.y), a0[base + 1]);
            a0[base + 2] = __hfma2(uh2(whr[0][c * 4 + 2]), uh2(hv.z), a0[base + 2]);
            a0[base + 3] = __hfma2(uh2(whr[0][c * 4 + 3]), uh2(hv.w), a0[base + 3]);
            a1[base + 0] = __hfma2(uh2(whr[1][c * 4 + 0]), uh2(hv.x), a1[base + 0]);
            a1[base + 1] = __hfma2(uh2(whr[1][c * 4 + 1]), uh2(hv.y), a1[base + 1]);
            a1[base + 2] = __hfma2(uh2(whr[1][c * 4 + 2]), uh2(hv.z), a1[base + 2]);
            a1[base + 3] = __hfma2(uh2(whr[1][c * 4 + 3]), uh2(hv.w), a1[base + 3]);
        }

        // fp32 pairwise reduction (same order as R11 per gate)
        float z0, z1;
        {
            float2 f0 = __half22float2(a0[0]);
            float2 f1 = __half22float2(a0[1]);
            float2 f2 = __half22float2(a0[2]);
            float2 f3 = __half22float2(a0[3]);
            float2 f4 = __half22float2(a0[4]);
            float2 f5 = __half22float2(a0[5]);
            float2 f6 = __half22float2(a0[6]);
            float2 f7 = __half22float2(a0[7]);
            float s01 = (f0.x + f0.y) + (f1.x + f1.y);
            float s23 = (f2.x + f2.y) + (f3.x + f3.y);
            float s45 = (f4.x + f4.y) + (f5.x + f5.y);
            float s67 = (f6.x + f6.y) + (f7.x + f7.y);
            z0 = gcur0 + (s01 + s23) + (s45 + s67);
        }
        {
            float2 f0 = __half22float2(a1[0]);
            float2 f1 = __half22float2(a1[1]);
            float2 f2 = __half22float2(a1[2]);
            float2 f3 = __half22float2(a1[3]);
            float2 f4 = __half22float2(a1[4]);
            float2 f5 = __half22float2(a1[5]);
            float2 f6 = __half22float2(a1[6]);
            float2 f7 = __half22float2(a1[7]);
            float s01 = (f0.x + f0.y) + (f1.x + f1.y);
            float s23 = (f2.x + f2.y) + (f3.x + f3.y);
            float s45 = (f4.x + f4.y) + (f5.x + f5.y);
            float s67 = (f6.x + f6.y) + (f7.x + f7.y);
            z1 = gcur1 + (s01 + s23) + (s45 + s67);
        }

        // activations in the parallel phase:
        // gate tid      : i (tid<128) or f         -> sigmoid
        // gate tid+256  : g (tid<128) or o         -> tanh / sigmoid
        float av0 = sigf(z0);
        float av1 = loGroup ? tanha(z1) : sigf(z1);
        *reinterpret_cast<float2*>(&zs[2 * tid]) = make_float2(av0, av1);
        __syncthreads();

        if (loGroup) {
            float2 v0 = *reinterpret_cast<const float2*>(&zs[2 * tid]);        // (a_i, a_g)
            float2 v1 = *reinterpret_cast<const float2*>(&zs[2 * (tid + 128)]); // (a_f, a_o)
            creg = v1.x * creg + v0.x * v0.y;
            float hv = v1.y * tanha(creg);
            hs[tid]  = hv;
            hsh[tid] = __float2half_rn(hv);
            if (layer == 0)
                g_out1h[(size_t)tok * 256 + dir * 128 + tid] = __float2half_rn(hv);
            else
                dout[(size_t)tok * 256 + dir * 128 + tid] = hv;
        }
        __syncthreads();

        tokb[cur] = toknew;
        g0b[cur]  = gnew0;
        g1b[cur]  = gnew1;
    }

    if (tid < 128) {
        float* hn = dout + (size_t)total * 256 + (size_t)kix * 8192 + (size_t)b * 128;
        float* cn = hn + 4 * 64 * 128;
        hn[tid] = hs[tid];
        cn[tid] = creg;
    }
}

// ---------------------------------------------------------------- launch ----
extern "C" void kernel_launch(void* const* d_in, const int* in_sizes, int n_in,
                              void* d_out, int out_size)
{
    const float* input       = (const float*)d_in[0];
    const int*   batch_sizes = (const int*)  d_in[1];
    const float* h0          = (const float*)d_in[2];
    const float* c0          = (const float*)d_in[3];
    const float* W_ih        = (const float*)d_in[4];
    const float* W_hh        = (const float*)d_in[5];
    const float* b_ih        = (const float*)d_in[6];
    const float* b_hh        = (const float*)d_in[7];
    float* out = (float*)d_out;

    int T     = in_sizes[1];
    int total = in_sizes[0] / 256;
    if (total > TOTAL_MAX) total = TOTAL_MAX;
    if (T > TMAX) T = TMAX;

    const int GEMM_SMEM = 2 * (2 * 128 * AK) * 2;                // 73728 B
    cudaFuncSetAttribute(gemm_hmma, cudaFuncAttributeMaxDynamicSharedMemorySize, GEMM_SMEM);

    setup_kernel<<<1, 1024>>>(batch_sizes, T);

    // fp16 prepass (single launch)
    __half* dA16;   cudaGetSymbolAddress((void**)&dA16, g_A16);
    __half* dW16;   cudaGetSymbolAddress((void**)&dW16, g_W16);
    __half* dOut1h; cudaGetSymbolAddress((void**)&dOut1h, g_out1h);
    {
        int n4a = in_sizes[0] / 4;
        int n4w = in_sizes[4] / 4;
        int n4  = n4a + n4w;
        cvt_kernel<<<(n4 + 255) / 256, 256>>>(input, dA16, n4a, W_ih, dW16, n4w);
    }

    dim3 ggrid((total + 127) / 128, 8);
    // layer 0
    gemm_hmma<<<ggrid, 256, GEMM_SMEM>>>(dA16, b_ih, b_hh, total, 0);
    rec_kernel<<<128, 256>>>(W_hh, h0, c0, out, total, T, 0);
    // layer 1
    gemm_hmma<<<ggrid, 256, GEMM_SMEM>>>(dOut1h, b_ih, b_hh, total, 1);
    rec_kernel<<<128, 256>>>(W_hh, h0, c0, out, total, T, 1);
}

// round 13
// speedup vs baseline: 1.0811x; 1.0811x over previous
#include <cuda_runtime.h>
#include <cuda_fp16.h>
#include <cstdint>

// ----------------------------------------------------------------------------
// Packed bidirectional 2-layer LSTM.
//   inputs : input(total,256) f32, batch_sizes(T) i32, h0(4,64,128), c0(4,64,128),
//            W_ih(4,512,256), W_hh(4,512,128), b_ih(4,512), b_hh(4,512)
//   outputs: packed_out(total,256) | h_n(4,64,128) | c_n(4,64,128)
// ----------------------------------------------------------------------------

#define TOTAL_MAX 49408
#define TMAX      1024
#define AK        72            // gemm smem stride in halves (144B, conflict-free)
#define KS        136           // rec smem stride in halves (272B, conflict-free)

__device__ float  g_gpre[2 * TOTAL_MAX * 512];
__device__ __half g_A16 [TOTAL_MAX * 256];      // layer-0 input, fp16
__device__ __half g_out1h[TOTAL_MAX * 256];     // layer-1 input (rec-l0 output), fp16
__device__ __half g_W16 [4 * 512 * 256];        // W_ih in fp16
__device__ int    g_offsets[TMAX];
__device__ int    g_len[64];

__device__ __forceinline__ __half2 uh2(unsigned int u)
{
    return *reinterpret_cast<__half2*>(&u);
}
__device__ __forceinline__ unsigned int h2u(__half2 h)
{
    return *reinterpret_cast<unsigned int*>(&h);
}

// ---- HMMA building blocks ----
__device__ __forceinline__ void cp16(uint32_t saddr, const void* gptr)
{
    asm volatile("cp.async.cg.shared.global [%0], [%1], 16;"
                 :: "r"(saddr), "l"(gptr) : "memory");
}
__device__ __forceinline__ void ldsm_x4(uint32_t& r0, uint32_t& r1,
                                        uint32_t& r2, uint32_t& r3, uint32_t addr)
{
    asm volatile("ldmatrix.sync.aligned.m8n8.x4.shared.b16 {%0,%1,%2,%3}, [%4];"
                 : "=r"(r0), "=r"(r1), "=r"(r2), "=r"(r3) : "r"(addr));
}
__device__ __forceinline__ void ldsm_x2(uint32_t& r0, uint32_t& r1, uint32_t addr)
{
    asm volatile("ldmatrix.sync.aligned.m8n8.x2.shared.b16 {%0,%1}, [%2];"
                 : "=r"(r0), "=r"(r1) : "r"(addr));
}
__device__ __forceinline__ void mma16816(float* c,
                                         uint32_t a0, uint32_t a1, uint32_t a2, uint32_t a3,
                                         uint32_t b0, uint32_t b1)
{
    asm volatile("mma.sync.aligned.m16n8k16.row.col.f32.f16.f16.f32 "
                 "{%0,%1,%2,%3}, {%4,%5,%6,%7}, {%8,%9}, {%0,%1,%2,%3};"
                 : "+f"(c[0]), "+f"(c[1]), "+f"(c[2]), "+f"(c[3])
                 : "r"(a0), "r"(a1), "r"(a2), "r"(a3), "r"(b0), "r"(b1));
}

// ---------------------------------------------------------------- setup -----
__global__ void setup_kernel(const int* __restrict__ bs, int T)
{
    __shared__ int s[TMAX];
    int tid = threadIdx.x;
    if (tid < T) s[tid] = bs[tid];
    __syncthreads();
    if (tid == 0) {
        int off = 0;
        for (int t = 0; t < T; ++t) { g_offsets[t] = off; off += s[t]; }
    }
    if (tid < 64) {
        int c = 0;
        for (int t = 0; t < T; ++t) c += (s[t] > tid) ? 1 : 0;
        g_len[tid] = c;
    }
}

// f32 -> f16 bulk convert, both arrays in ONE launch.
__global__ void cvt_kernel(const float* __restrict__ srcA, __half* __restrict__ dstA, int n4a,
                           const float* __restrict__ srcW, __half* __restrict__ dstW, int n4w)
{
    int i = blockIdx.x * blockDim.x + threadIdx.x;
    const float* src;
    __half* dst;
    int j;
    if (i < n4a) { src = srcA; dst = dstA; j = i; }
    else if (i < n4a + n4w) { src = srcW; dst = dstW; j = i - n4a; }
    else return;
    float4 v = reinterpret_cast<const float4*>(src)[j];
    __half2 lo = __floats2half2_rn(v.x, v.y);
    __half2 hi = __floats2half2_rn(v.z, v.w);
    uint2 u;
    u.x = h2u(lo);
    u.y = h2u(hi);
    reinterpret_cast<uint2*>(dst)[j] = u;
}

// ------------------------------------------------------------ HMMA gemm -----
// (unchanged, known-good)
__global__ __launch_bounds__(256, 2)
void gemm_hmma(const __half* __restrict__ Ah,
               const float* __restrict__ bih_all,
               const float* __restrict__ bhh_all,
               int total, int layer)
{
    extern __shared__ __half shbuf[];
    const int STAGE = 2 * 128 * AK;
    const uint32_t sbase = (uint32_t)__cvta_generic_to_shared(shbuf);

    const __half* Wl = g_W16 + (size_t)layer * 262144;
    const float*  bi = bih_all + layer * 1024;
    const float*  bh = bhh_all + layer * 1024;

    const int tid   = threadIdx.x;
    const int lane  = tid & 31;
    const int wid   = tid >> 5;
    const int warpM = wid >> 2;
    const int warpN = wid & 3;
    const int mBase = blockIdx.x * 128;
    const int nBase = blockIdx.y * 128;

    const int r0 = tid >> 3;
    const int c0 = tid & 7;

    const int grp  = lane >> 3;
    const int rinl = lane & 7;
    const int aRow = warpM * 64 + (grp & 1) * 8 + rinl;
    const int aCol = (grp >> 1) * 8;
    const int bRowBase = warpN * 32 + rinl;
    const int bCol = ((lane >> 3) & 1) * 8;

    float acc[4][4][4];
#pragma unroll
    for (int i = 0; i < 4; ++i)
#pragma unroll
        for (int j = 0; j < 4; ++j)
#pragma unroll
            for (int v = 0; v < 4; ++v) acc[i][j][v] = 0.f;

#pragma unroll
    for (int i = 0; i < 4; ++i) {
        int r = r0 + i * 32;
        int arow = mBase + r;
        if (arow > total - 1) arow = total - 1;
        cp16(sbase + (uint32_t)(r * AK + c0 * 8) * 2,
             Ah + (size_t)arow * 256 + c0 * 8);
        cp16(sbase + (uint32_t)(128 * AK + r * AK + c0 * 8) * 2,
             Wl + (size_t)(nBase + r) * 256 + c0 * 8);
    }
    asm volatile("cp.async.commit_group;" ::: "memory");

    for (int s = 0; s < 4; ++s) {
        if (s < 3) {
            const int ks  = s + 1;
            const int nbf = ks & 1;
#pragma unroll
            for (int i = 0; i < 4; ++i) {
                int r = r0 + i * 32;
                int arow = mBase + r;
                if (arow > total - 1) arow = total - 1;
                cp16(sbase + (uint32_t)(nbf * STAGE + r * AK + c0 * 8) * 2,
                     Ah + (size_t)arow * 256 + ks * 64 + c0 * 8);
                cp16(sbase + (uint32_t)(nbf * STAGE + 128 * AK + r * AK + c0 * 8) * 2,
                     Wl + (size_t)(nBase + r) * 256 + ks * 64 + c0 * 8);
            }
        }
        asm volatile("cp.async.commit_group;" ::: "memory");
        if (s < 3) asm volatile("cp.async.wait_group 1;" ::: "memory");
        else       asm volatile("cp.async.wait_group 0;" ::: "memory");
        __syncthreads();

        const int buf = s & 1;
        const uint32_t aTile = sbase + (uint32_t)(buf * STAGE) * 2;
        const uint32_t bTile = sbase + (uint32_t)(buf * STAGE + 128 * AK) * 2;

#pragma unroll
        for (int kk = 0; kk < 4; ++kk) {
            uint32_t af[4][4];
            uint32_t bf[4][2];
#pragma unroll
            for (int mf = 0; mf < 4; ++mf) {
                uint32_t aaddr = aTile +
                    (uint32_t)((aRow + mf * 16) * AK + kk * 16 + aCol) * 2;
                ldsm_x4(af[mf][0], af[mf][1], af[mf][2], af[mf][3], aaddr);
            }
#pragma unroll
            for (int nf = 0; nf < 4; ++nf) {
                uint32_t baddr = bTile +
                    (uint32_t)((bRowBase + nf * 8) * AK + kk * 16 + bCol) * 2;
                ldsm_x2(bf[nf][0], bf[nf][1], baddr);
            }
#pragma unroll
            for (int mf = 0; mf < 4; ++mf)
#pragma unroll
                for (int nf = 0; nf < 4; ++nf)
                    mma16816(acc[mf][nf],
                             af[mf][0], af[mf][1], af[mf][2], af[mf][3],
                             bf[nf][0], bf[nf][1]);
        }
        __syncthreads();
    }

    const int mW = mBase + warpM * 64 + (lane >> 2);
    const int nW = nBase + warpN * 32 + ((lane & 3) << 1);
#pragma unroll
    for (int nf = 0; nf < 4; ++nf) {
        int n = nW + nf * 8;
        float bias0 = bi[n] + bh[n];
        float bias1 = bi[n + 1] + bh[n + 1];
        int dirr = n >> 9;
        int g    = n & 511;
        float* gp = g_gpre + (size_t)dirr * (size_t)total * 512 + g;
#pragma unroll
        for (int mf = 0; mf < 4; ++mf) {
            int m0 = mW + mf * 16;
            if (m0 < total) {
                float2 v = make_float2(acc[mf][nf][0] + bias0, acc[mf][nf][1] + bias1);
                *reinterpret_cast<float2*>(gp + (size_t)m0 * 512) = v;
            }
            int m1 = m0 + 8;
            if (m1 < total) {
                float2 v = make_float2(acc[mf][nf][2] + bias0, acc[mf][nf][3] + bias1);
                *reinterpret_cast<float2*>(gp + (size_t)m1 * 512) = v;
            }
        }
    }
}

// ------------------------------------------------------------- recurrence ---
__device__ __forceinline__ float tanha(float x)
{
    float y;
    asm("tanh.approx.f32 %0, %1;" : "=f"(y) : "f"(x));
    return y;
}
__device__ __forceinline__ float sigf(float x)
{
    return fmaf(tanha(0.5f * x), 0.5f, 0.5f);
}

// Tensor-core recurrence. 128 CTAs: blockIdx.x = dir*64 + b. 256 threads.
// Warp w owns row-tiles {gate m at rows m*128 + [16w,16w+16)} -> after the
// mma, lane 4j holds ALL FOUR gate z's for cells 16w+j and 16w+j+8 in col 0
// of its C fragments. No z exchange, no z barrier. B = h as (n,k) 8x128 tile
// (row 0 = h fp16, rows 1-7 zero), ping-pong buffers -> ONE barrier/step.
// gpre (gemm result + biases) is the C initializer, prefetched 1 step ahead.
__global__ __launch_bounds__(256, 1)
void rec_kernel(const float* __restrict__ Whh_all,
                const float* __restrict__ h0,
                const float* __restrict__ c0,
                float* __restrict__ dout,
                int total, int T, int layer)
{
    extern __shared__ char rsm[];
    __half* sW = reinterpret_cast<__half*>(rsm);                 // 512*KS halves = 139264 B
    __half* hB = reinterpret_cast<__half*>(rsm + 512 * KS * 2);  // 2 bufs * 8*KS halves = 4352 B
    int*  offs = reinterpret_cast<int*>(rsm + 512 * KS * 2 + 2 * 8 * KS * 2);

    const int tid  = threadIdx.x;
    const int lane = tid & 31;
    const int w    = tid >> 5;
    const int dir  = blockIdx.x >> 6;
    const int b    = blockIdx.x & 63;
    const int kix  = 2 * layer + dir;

    const float* gpd = g_gpre + (size_t)dir * (size_t)total * 512;
    const float* W   = Whh_all + (size_t)kix * 512 * 128;

    for (int i = tid; i < T; i += 256) offs[i] = g_offsets[i];

    // zero both hB buffers (rows 1-7 stay zero forever)
    for (int i = tid; i < 2 * 8 * KS; i += 256)
        hB[i] = __ushort_as_half((unsigned short)0);

    // stage W (fp32 -> fp16) into sW, row-major stride KS
    for (int i = tid; i < 512 * 32; i += 256) {
        int r = i >> 5, q = i & 31;
        float4 v = *reinterpret_cast<const float4*>(&W[r * 128 + q * 4]);
        __half2 lo = __floats2half2_rn(v.x, v.y);
        __half2 hi = __floats2half2_rn(v.z, v.w);
        uint2 u;
        u.x = h2u(lo);
        u.y = h2u(hi);
        *reinterpret_cast<uint2*>(&sW[r * KS + q * 4]) = u;
    }

    // h0 -> hB buffer 0 row 0 (fp16)
    if (tid < 128)
        hB[tid] = __float2half_rn(h0[(size_t)kix * 8192 + b * 128 + tid]);
    __syncthreads();

    // ---- load A fragments (W) into registers, once
    const uint32_t sWb = (uint32_t)__cvta_generic_to_shared(sW);
    const int grp = lane >> 3, rinl = lane & 7;
    uint32_t afr[4][8][4];
#pragma unroll
    for (int m = 0; m < 4; ++m)
#pragma unroll
        for (int kk = 0; kk < 8; ++kk) {
            uint32_t aaddr = sWb +
                (uint32_t)((m * 128 + 16 * w + (grp & 1) * 8 + rinl) * KS
                           + (grp >> 1) * 8 + kk * 16) * 2;
            ldsm_x4(afr[m][kk][0], afr[m][kk][1], afr[m][kk][2], afr[m][kk][3], aaddr);
        }

    const uint32_t hBb = (uint32_t)__cvta_generic_to_shared(hB);
    const uint32_t bOffLane = (uint32_t)((rinl * KS + ((lane >> 3) & 1) * 8) * 2);

    const bool act   = ((lane & 3) == 0);
    const int  cell0 = 16 * w + (lane >> 2);   // valid on act lanes
    const int  cell1 = cell0 + 8;

    float creg0 = 0.f, creg1 = 0.f;
    if (act) {
        creg0 = c0[(size_t)kix * 8192 + b * 128 + cell0];
        creg1 = c0[(size_t)kix * 8192 + b * 128 + cell1];
    }

    const int  len = g_len[b];
    const bool fwd = (dir == 0);

    // preload gpre for step 0
    int tok = offs[fwd ? 0 : (len - 1)] + b;
    float gp0[4], gp1[4];
#pragma unroll
    for (int m = 0; m < 4; ++m) { gp0[m] = 0.f; gp1[m] = 0.f; }
    if (act) {
        const float* g = gpd + (size_t)tok * 512;
#pragma unroll
        for (int m = 0; m < 4; ++m) {
            gp0[m] = g[m * 128 + cell0];
            gp1[m] = g[m * 128 + cell1];
        }
    }

    float hreg0 = 0.f, hreg1 = 0.f;
    int p = 0;

    for (int s = 0; s < len; ++s) {
        // prefetch gpre for step s+1
        int   toknext = 0;
        float gn0[4], gn1[4];
#pragma unroll
        for (int m = 0; m < 4; ++m) { gn0[m] = 0.f; gn1[m] = 0.f; }
        if (s + 1 < len) {
            int tn  = fwd ? (s + 1) : (len - 2 - s);
            toknext = offs[tn] + b;
            if (act) {
                const float* g = gpd + (size_t)toknext * 512;
#pragma unroll
                for (int m = 0; m < 4; ++m) {
                    gn0[m] = g[m * 128 + cell0];
                    gn1[m] = g[m * 128 + cell1];
                }
            }
        }

        // B fragments: h (buffer p)
        uint32_t bb = hBb + (uint32_t)(p * 8 * KS * 2) + bOffLane;
        uint32_t bf[8][2];
#pragma unroll
        for (int kk = 0; kk < 8; ++kk)
            ldsm_x2(bf[kk][0], bf[kk][1], bb + kk * 32);

        // C init = gpre (col 0 only; other cols dead)
        float c[4][4];
#pragma unroll
        for (int m = 0; m < 4; ++m) {
            c[m][0] = gp0[m];
            c[m][1] = 0.f;
            c[m][2] = gp1[m];
            c[m][3] = 0.f;
        }

#pragma unroll
        for (int kk = 0; kk < 8; ++kk)
#pragma unroll
            for (int m = 0; m < 4; ++m)
                mma16816(c[m], afr[m][kk][0], afr[m][kk][1], afr[m][kk][2], afr[m][kk][3],
                         bf[kk][0], bf[kk][1]);

        // gates: lane 4j has zi/zf/zg/zo for cells 16w+j (c[m][0]) and +8 (c[m][2])
        if (act) {
            float ig = sigf(c[0][0]);
            float fg = sigf(c[1][0]);
            float gv = tanha(c[2][0]);
            float og = sigf(c[3][0]);
            creg0 = fg * creg0 + ig * gv;
            hreg0 = og * tanha(creg0);

            float ig1 = sigf(c[0][2]);
            float fg1 = sigf(c[1][2]);
            float gv1 = tanha(c[2][2]);
            float og1 = sigf(c[3][2]);
            creg1 = fg1 * creg1 + ig1 * gv1;
            hreg1 = og1 * tanha(creg1);

            __half hh0 = __float2half_rn(hreg0);
            __half hh1 = __float2half_rn(hreg1);
            __half* hdst = hB + (p ^ 1) * 8 * KS;
            hdst[cell0] = hh0;
            hdst[cell1] = hh1;

            if (layer == 0) {
                g_out1h[(size_t)tok * 256 + dir * 128 + cell0] = hh0;
                g_out1h[(size_t)tok * 256 + dir * 128 + cell1] = hh1;
            } else {
                dout[(size_t)tok * 256 + dir * 128 + cell0] = hreg0;
                dout[(size_t)tok * 256 + dir * 128 + cell1] = hreg1;
            }
        }
        __syncthreads();
        p ^= 1;
        tok = toknext;
#pragma unroll
        for (int m = 0; m < 4; ++m) { gp0[m] = gn0[m]; gp1[m] = gn1[m]; }
    }

    if (act) {
        float* hn = dout + (size_t)total * 256 + (size_t)kix * 8192 + (size_t)b * 128;
        float* cn = hn + 4 * 64 * 128;
        hn[cell0] = hreg0;
        hn[cell1] = hreg1;
        cn[cell0] = creg0;
        cn[cell1] = creg1;
    }
}

// ---------------------------------------------------------------- launch ----
extern "C" void kernel_launch(void* const* d_in, const int* in_sizes, int n_in,
                              void* d_out, int out_size)
{
    const float* input       = (const float*)d_in[0];
    const int*   batch_sizes = (const int*)  d_in[1];
    const float* h0          = (const float*)d_in[2];
    const float* c0          = (const float*)d_in[3];
    const float* W_ih        = (const float*)d_in[4];
    const float* W_hh        = (const float*)d_in[5];
    const float* b_ih        = (const float*)d_in[6];
    const float* b_hh        = (const float*)d_in[7];
    float* out = (float*)d_out;

    int T     = in_sizes[1];
    int total = in_sizes[0] / 256;
    if (total > TOTAL_MAX) total = TOTAL_MAX;
    if (T > TMAX) T = TMAX;

    const int GEMM_SMEM = 2 * (2 * 128 * AK) * 2;                     // 73728 B
    const int REC_SMEM  = 512 * KS * 2 + 2 * 8 * KS * 2 + TMAX * 4;   // 147712 B
    cudaFuncSetAttribute(gemm_hmma, cudaFuncAttributeMaxDynamicSharedMemorySize, GEMM_SMEM);
    cudaFuncSetAttribute(rec_kernel, cudaFuncAttributeMaxDynamicSharedMemorySize, REC_SMEM);

    setup_kernel<<<1, 1024>>>(batch_sizes, T);

    // fp16 prepass (single launch)
    __half* dA16;   cudaGetSymbolAddress((void**)&dA16, g_A16);
    __half* dW16;   cudaGetSymbolAddress((void**)&dW16, g_W16);
    __half* dOut1h; cudaGetSymbolAddress((void**)&dOut1h, g_out1h);
    {
        int n4a = in_sizes[0] / 4;
        int n4w = in_sizes[4] / 4;
        int n4  = n4a + n4w;
        cvt_kernel<<<(n4 + 255) / 256, 256>>>(input, dA16, n4a, W_ih, dW16, n4w);
    }

    dim3 ggrid((total + 127) / 128, 8);
    // layer 0
    gemm_hmma<<<ggrid, 256, GEMM_SMEM>>>(dA16, b_ih, b_hh, total, 0);
    rec_kernel<<<128, 256, REC_SMEM>>>(W_hh, h0, c0, out, total, T, 0);
    // layer 1
    gemm_hmma<<<ggrid, 256, GEMM_SMEM>>>(dOut1h, b_ih, b_hh, total, 1);
    rec_kernel<<<128, 256, REC_SMEM>>>(W_hh, h0, c0, out, total, T, 1);
}

// round 14
// speedup vs baseline: 1.0851x; 1.0037x over previous
#include <cuda_runtime.h>
#include <cuda_fp16.h>
#include <cstdint>

// ----------------------------------------------------------------------------
// Packed bidirectional 2-layer LSTM.
//   inputs : input(total,256) f32, batch_sizes(T) i32, h0(4,64,128), c0(4,64,128),
//            W_ih(4,512,256), W_hh(4,512,128), b_ih(4,512), b_hh(4,512)
//   outputs: packed_out(total,256) | h_n(4,64,128) | c_n(4,64,128)
// ----------------------------------------------------------------------------

#define TOTAL_MAX 49408
#define TMAX      1024
#define AK        72            // gemm smem stride in halves (144B, conflict-free)
#define KS        136           // rec smem stride in halves (272B, conflict-free)

__device__ float  g_gpre[2 * TOTAL_MAX * 512];
__device__ __half g_A16 [TOTAL_MAX * 256];      // layer-0 input, fp16
__device__ __half g_out1h[TOTAL_MAX * 256];     // layer-1 input (rec-l0 output), fp16
__device__ __half g_W16 [4 * 512 * 256];        // W_ih in fp16
__device__ int    g_offsets[TMAX];
__device__ int    g_len[64];

__device__ __forceinline__ __half2 uh2(unsigned int u)
{
    return *reinterpret_cast<__half2*>(&u);
}
__device__ __forceinline__ unsigned int h2u(__half2 h)
{
    return *reinterpret_cast<unsigned int*>(&h);
}

// ---- HMMA building blocks ----
__device__ __forceinline__ void cp16(uint32_t saddr, const void* gptr)
{
    asm volatile("cp.async.cg.shared.global [%0], [%1], 16;"
                 :: "r"(saddr), "l"(gptr) : "memory");
}
__device__ __forceinline__ void ldsm_x4(uint32_t& r0, uint32_t& r1,
                                        uint32_t& r2, uint32_t& r3, uint32_t addr)
{
    asm volatile("ldmatrix.sync.aligned.m8n8.x4.shared.b16 {%0,%1,%2,%3}, [%4];"
                 : "=r"(r0), "=r"(r1), "=r"(r2), "=r"(r3) : "r"(addr));
}
__device__ __forceinline__ void ldsm_x2(uint32_t& r0, uint32_t& r1, uint32_t addr)
{
    asm volatile("ldmatrix.sync.aligned.m8n8.x2.shared.b16 {%0,%1}, [%2];"
                 : "=r"(r0), "=r"(r1) : "r"(addr));
}
__device__ __forceinline__ void mma16816(float* c,
                                         uint32_t a0, uint32_t a1, uint32_t a2, uint32_t a3,
                                         uint32_t b0, uint32_t b1)
{
    asm volatile("mma.sync.aligned.m16n8k16.row.col.f32.f16.f16.f32 "
                 "{%0,%1,%2,%3}, {%4,%5,%6,%7}, {%8,%9}, {%0,%1,%2,%3};"
                 : "+f"(c[0]), "+f"(c[1]), "+f"(c[2]), "+f"(c[3])
                 : "r"(a0), "r"(a1), "r"(a2), "r"(a3), "r"(b0), "r"(b1));
}
// fp16-accumulator variant: D/C are 2 regs (4 halves)
__device__ __forceinline__ void mma16816h(uint32_t& d0, uint32_t& d1,
                                          uint32_t a0, uint32_t a1, uint32_t a2, uint32_t a3,
                                          uint32_t b0, uint32_t b1)
{
    asm volatile("mma.sync.aligned.m16n8k16.row.col.f16.f16.f16.f16 "
                 "{%0,%1}, {%2,%3,%4,%5}, {%6,%7}, {%0,%1};"
                 : "+r"(d0), "+r"(d1)
                 : "r"(a0), "r"(a1), "r"(a2), "r"(a3), "r"(b0), "r"(b1));
}

// ---------------------------------------------------------------- setup -----
__global__ void setup_kernel(const int* __restrict__ bs, int T)
{
    __shared__ int s[TMAX];
    int tid = threadIdx.x;
    if (tid < T) s[tid] = bs[tid];
    __syncthreads();
    if (tid == 0) {
        int off = 0;
        for (int t = 0; t < T; ++t) { g_offsets[t] = off; off += s[t]; }
    }
    if (tid < 64) {
        int c = 0;
        for (int t = 0; t < T; ++t) c += (s[t] > tid) ? 1 : 0;
        g_len[tid] = c;
    }
}

// f32 -> f16 bulk convert, both arrays in ONE launch.
__global__ void cvt_kernel(const float* __restrict__ srcA, __half* __restrict__ dstA, int n4a,
                           const float* __restrict__ srcW, __half* __restrict__ dstW, int n4w)
{
    int i = blockIdx.x * blockDim.x + threadIdx.x;
    const float* src;
    __half* dst;
    int j;
    if (i < n4a) { src = srcA; dst = dstA; j = i; }
    else if (i < n4a + n4w) { src = srcW; dst = dstW; j = i - n4a; }
    else return;
    float4 v = reinterpret_cast<const float4*>(src)[j];
    __half2 lo = __floats2half2_rn(v.x, v.y);
    __half2 hi = __floats2half2_rn(v.z, v.w);
    uint2 u;
    u.x = h2u(lo);
    u.y = h2u(hi);
    reinterpret_cast<uint2*>(dst)[j] = u;
}

// ------------------------------------------------------------ HMMA gemm -----
// (unchanged, known-good)
__global__ __launch_bounds__(256, 2)
void gemm_hmma(const __half* __restrict__ Ah,
               const float* __restrict__ bih_all,
               const float* __restrict__ bhh_all,
               int total, int layer)
{
    extern __shared__ __half shbuf[];
    const int STAGE = 2 * 128 * AK;
    const uint32_t sbase = (uint32_t)__cvta_generic_to_shared(shbuf);

    const __half* Wl = g_W16 + (size_t)layer * 262144;
    const float*  bi = bih_all + layer * 1024;
    const float*  bh = bhh_all + layer * 1024;

    const int tid   = threadIdx.x;
    const int lane  = tid & 31;
    const int wid   = tid >> 5;
    const int warpM = wid >> 2;
    const int warpN = wid & 3;
    const int mBase = blockIdx.x * 128;
    const int nBase = blockIdx.y * 128;

    const int r0 = tid >> 3;
    const int c0 = tid & 7;

    const int grp  = lane >> 3;
    const int rinl = lane & 7;
    const int aRow = warpM * 64 + (grp & 1) * 8 + rinl;
    const int aCol = (grp >> 1) * 8;
    const int bRowBase = warpN * 32 + rinl;
    const int bCol = ((lane >> 3) & 1) * 8;

    float acc[4][4][4];
#pragma unroll
    for (int i = 0; i < 4; ++i)
#pragma unroll
        for (int j = 0; j < 4; ++j)
#pragma unroll
            for (int v = 0; v < 4; ++v) acc[i][j][v] = 0.f;

#pragma unroll
    for (int i = 0; i < 4; ++i) {
        int r = r0 + i * 32;
        int arow = mBase + r;
        if (arow > total - 1) arow = total - 1;
        cp16(sbase + (uint32_t)(r * AK + c0 * 8) * 2,
             Ah + (size_t)arow * 256 + c0 * 8);
        cp16(sbase + (uint32_t)(128 * AK + r * AK + c0 * 8) * 2,
             Wl + (size_t)(nBase + r) * 256 + c0 * 8);
    }
    asm volatile("cp.async.commit_group;" ::: "memory");

    for (int s = 0; s < 4; ++s) {
        if (s < 3) {
            const int ks  = s + 1;
            const int nbf = ks & 1;
#pragma unroll
            for (int i = 0; i < 4; ++i) {
                int r = r0 + i * 32;
                int arow = mBase + r;
                if (arow > total - 1) arow = total - 1;
                cp16(sbase + (uint32_t)(nbf * STAGE + r * AK + c0 * 8) * 2,
                     Ah + (size_t)arow * 256 + ks * 64 + c0 * 8);
                cp16(sbase + (uint32_t)(nbf * STAGE + 128 * AK + r * AK + c0 * 8) * 2,
                     Wl + (size_t)(nBase + r) * 256 + ks * 64 + c0 * 8);
            }
        }
        asm volatile("cp.async.commit_group;" ::: "memory");
        if (s < 3) asm volatile("cp.async.wait_group 1;" ::: "memory");
        else       asm volatile("cp.async.wait_group 0;" ::: "memory");
        __syncthreads();

        const int buf = s & 1;
        const uint32_t aTile = sbase + (uint32_t)(buf * STAGE) * 2;
        const uint32_t bTile = sbase + (uint32_t)(buf * STAGE + 128 * AK) * 2;

#pragma unroll
        for (int kk = 0; kk < 4; ++kk) {
            uint32_t af[4][4];
            uint32_t bf[4][2];
#pragma unroll
            for (int mf = 0; mf < 4; ++mf) {
                uint32_t aaddr = aTile +
                    (uint32_t)((aRow + mf * 16) * AK + kk * 16 + aCol) * 2;
                ldsm_x4(af[mf][0], af[mf][1], af[mf][2], af[mf][3], aaddr);
            }
#pragma unroll
            for (int nf = 0; nf < 4; ++nf) {
                uint32_t baddr = bTile +
                    (uint32_t)((bRowBase + nf * 8) * AK + kk * 16 + bCol) * 2;
                ldsm_x2(bf[nf][0], bf[nf][1], baddr);
            }
#pragma unroll
            for (int mf = 0; mf < 4; ++mf)
#pragma unroll
                for (int nf = 0; nf < 4; ++nf)
                    mma16816(acc[mf][nf],
                             af[mf][0], af[mf][1], af[mf][2], af[mf][3],
                             bf[nf][0], bf[nf][1]);
        }
        __syncthreads();
    }

    const int mW = mBase + warpM * 64 + (lane >> 2);
    const int nW = nBase + warpN * 32 + ((lane & 3) << 1);
#pragma unroll
    for (int nf = 0; nf < 4; ++nf) {
        int n = nW + nf * 8;
        float bias0 = bi[n] + bh[n];
        float bias1 = bi[n + 1] + bh[n + 1];
        int dirr = n >> 9;
        int g    = n & 511;
        float* gp = g_gpre + (size_t)dirr * (size_t)total * 512 + g;
#pragma unroll
        for (int mf = 0; mf < 4; ++mf) {
            int m0 = mW + mf * 16;
            if (m0 < total) {
                float2 v = make_float2(acc[mf][nf][0] + bias0, acc[mf][nf][1] + bias1);
                *reinterpret_cast<float2*>(gp + (size_t)m0 * 512) = v;
            }
            int m1 = m0 + 8;
            if (m1 < total) {
                float2 v = make_float2(acc[mf][nf][2] + bias0, acc[mf][nf][3] + bias1);
                *reinterpret_cast<float2*>(gp + (size_t)m1 * 512) = v;
            }
        }
    }
}

// ------------------------------------------------------------- recurrence ---
__device__ __forceinline__ float tanha(float x)
{
    float y;
    asm("tanh.approx.f32 %0, %1;" : "=f"(y) : "f"(x));
    return y;
}
__device__ __forceinline__ float sigf(float x)
{
    return fmaf(tanha(0.5f * x), 0.5f, 0.5f);
}

// Tensor-core recurrence (fp16-accumulator MMA). 128 CTAs: dir*64 + b.
// Warp w owns row-tiles {gate m at rows m*128 + [16w,16w+16)}. Two 4-deep
// k-chains per m-tile (ILP); z = gpre(f32) + f32(chainA) + f32(chainB).
// B = h as (n,k) 8x128 tile (row 0 = h fp16, rows 1-7 zero), ping-pong
// buffers -> ONE barrier/step. gpre prefetched 1 step ahead.
__global__ __launch_bounds__(256, 1)
void rec_kernel(const float* __restrict__ Whh_all,
                const float* __restrict__ h0,
                const float* __restrict__ c0,
                float* __restrict__ dout,
                int total, int T, int layer)
{
    extern __shared__ char rsm[];
    __half* sW = reinterpret_cast<__half*>(rsm);                 // 512*KS halves
    __half* hB = reinterpret_cast<__half*>(rsm + 512 * KS * 2);  // 2 bufs * 8*KS halves
    int*  offs = reinterpret_cast<int*>(rsm + 512 * KS * 2 + 2 * 8 * KS * 2);

    const int tid  = threadIdx.x;
    const int lane = tid & 31;
    const int w    = tid >> 5;
    const int dir  = blockIdx.x >> 6;
    const int b    = blockIdx.x & 63;
    const int kix  = 2 * layer + dir;

    const float* gpd = g_gpre + (size_t)dir * (size_t)total * 512;
    const float* W   = Whh_all + (size_t)kix * 512 * 128;

    for (int i = tid; i < T; i += 256) offs[i] = g_offsets[i];

    // zero both hB buffers (rows 1-7 stay zero forever)
    for (int i = tid; i < 2 * 8 * KS; i += 256)
        hB[i] = __ushort_as_half((unsigned short)0);

    // stage W (fp32 -> fp16) into sW, row-major stride KS
    for (int i = tid; i < 512 * 32; i += 256) {
        int r = i >> 5, q = i & 31;
        float4 v = *reinterpret_cast<const float4*>(&W[r * 128 + q * 4]);
        __half2 lo = __floats2half2_rn(v.x, v.y);
        __half2 hi = __floats2half2_rn(v.z, v.w);
        uint2 u;
        u.x = h2u(lo);
        u.y = h2u(hi);
        *reinterpret_cast<uint2*>(&sW[r * KS + q * 4]) = u;
    }

    // h0 -> hB buffer 0 row 0 (fp16)
    if (tid < 128)
        hB[tid] = __float2half_rn(h0[(size_t)kix * 8192 + b * 128 + tid]);
    __syncthreads();

    // ---- load A fragments (W) into registers, once
    const uint32_t sWb = (uint32_t)__cvta_generic_to_shared(sW);
    const int grp = lane >> 3, rinl = lane & 7;
    uint32_t afr[4][8][4];
#pragma unroll
    for (int m = 0; m < 4; ++m)
#pragma unroll
        for (int kk = 0; kk < 8; ++kk) {
            uint32_t aaddr = sWb +
                (uint32_t)((m * 128 + 16 * w + (grp & 1) * 8 + rinl) * KS
                           + (grp >> 1) * 8 + kk * 16) * 2;
            ldsm_x4(afr[m][kk][0], afr[m][kk][1], afr[m][kk][2], afr[m][kk][3], aaddr);
        }

    const uint32_t hBb = (uint32_t)__cvta_generic_to_shared(hB);
    const uint32_t bOffLane = (uint32_t)((rinl * KS + ((lane >> 3) & 1) * 8) * 2);

    const bool act   = ((lane & 3) == 0);
    const int  cell0 = 16 * w + (lane >> 2);   // valid on act lanes
    const int  cell1 = cell0 + 8;

    float creg0 = 0.f, creg1 = 0.f;
    if (act) {
        creg0 = c0[(size_t)kix * 8192 + b * 128 + cell0];
        creg1 = c0[(size_t)kix * 8192 + b * 128 + cell1];
    }

    const int  len = g_len[b];
    const bool fwd = (dir == 0);

    // preload gpre for step 0
    int tok = offs[fwd ? 0 : (len - 1)] + b;
    float gp0[4], gp1[4];
#pragma unroll
    for (int m = 0; m < 4; ++m) { gp0[m] = 0.f; gp1[m] = 0.f; }
    if (act) {
        const float* g = gpd + (size_t)tok * 512;
#pragma unroll
        for (int m = 0; m < 4; ++m) {
            gp0[m] = g[m * 128 + cell0];
            gp1[m] = g[m * 128 + cell1];
        }
    }

    float hreg0 = 0.f, hreg1 = 0.f;
    int p = 0;

    for (int s = 0; s < len; ++s) {
        // prefetch gpre for step s+1
        int   toknext = 0;
        float gn0[4], gn1[4];
#pragma unroll
        for (int m = 0; m < 4; ++m) { gn0[m] = 0.f; gn1[m] = 0.f; }
        if (s + 1 < len) {
            int tn  = fwd ? (s + 1) : (len - 2 - s);
            toknext = offs[tn] + b;
            if (act) {
                const float* g = gpd + (size_t)toknext * 512;
#pragma unroll
                for (int m = 0; m < 4; ++m) {
                    gn0[m] = g[m * 128 + cell0];
                    gn1[m] = g[m * 128 + cell1];
                }
            }
        }

        // B fragments: h (buffer p)
        uint32_t bb = hBb + (uint32_t)(p * 8 * KS * 2) + bOffLane;
        uint32_t bf[8][2];
#pragma unroll
        for (int kk = 0; kk < 8; ++kk)
            ldsm_x2(bf[kk][0], bf[kk][1], bb + kk * 32);

        // two independent 4-deep fp16 accumulation chains per m-tile
        uint32_t cA[4][2], cB[4][2];
#pragma unroll
        for (int m = 0; m < 4; ++m) {
            cA[m][0] = 0u; cA[m][1] = 0u;
            cB[m][0] = 0u; cB[m][1] = 0u;
        }
#pragma unroll
        for (int kk = 0; kk < 4; ++kk)
#pragma unroll
            for (int m = 0; m < 4; ++m)
                mma16816h(cA[m][0], cA[m][1],
                          afr[m][kk][0], afr[m][kk][1], afr[m][kk][2], afr[m][kk][3],
                          bf[kk][0], bf[kk][1]);
#pragma unroll
        for (int kk = 4; kk < 8; ++kk)
#pragma unroll
            for (int m = 0; m < 4; ++m)
                mma16816h(cB[m][0], cB[m][1],
                          afr[m][kk][0], afr[m][kk][1], afr[m][kk][2], afr[m][kk][3],
                          bf[kk][0], bf[kk][1]);

        // gates: lane 4j has col-0 halves for cells 16w+j (reg 0) and +8 (reg 1)
        if (act) {
            float z0[4], z1[4];
#pragma unroll
            for (int m = 0; m < 4; ++m) {
                z0[m] = gp0[m] + __half2float(__low2half(uh2(cA[m][0])))
                               + __half2float(__low2half(uh2(cB[m][0])));
                z1[m] = gp1[m] + __half2float(__low2half(uh2(cA[m][1])))
                               + __half2float(__low2half(uh2(cB[m][1])));
            }
            float ig = sigf(z0[0]);
            float fg = sigf(z0[1]);
            float gv = tanha(z0[2]);
            float og = sigf(z0[3]);
            creg0 = fg * creg0 + ig * gv;
            hreg0 = og * tanha(creg0);

            float ig1 = sigf(z1[0]);
            float fg1 = sigf(z1[1]);
            float gv1 = tanha(z1[2]);
            float og1 = sigf(z1[3]);
            creg1 = fg1 * creg1 + ig1 * gv1;
            hreg1 = og1 * tanha(creg1);

            __half hh0 = __float2half_rn(hreg0);
            __half hh1 = __float2half_rn(hreg1);
            __half* hdst = hB + (p ^ 1) * 8 * KS;
            hdst[cell0] = hh0;
            hdst[cell1] = hh1;

            if (layer == 0) {
                g_out1h[(size_t)tok * 256 + dir * 128 + cell0] = hh0;
                g_out1h[(size_t)tok * 256 + dir * 128 + cell1] = hh1;
            } else {
                dout[(size_t)tok * 256 + dir * 128 + cell0] = hreg0;
                dout[(size_t)tok * 256 + dir * 128 + cell1] = hreg1;
            }
        }
        __syncthreads();
        p ^= 1;
        tok = toknext;
#pragma unroll
        for (int m = 0; m < 4; ++m) { gp0[m] = gn0[m]; gp1[m] = gn1[m]; }
    }

    if (act) {
        float* hn = dout + (size_t)total * 256 + (size_t)kix * 8192 + (size_t)b * 128;
        float* cn = hn + 4 * 64 * 128;
        hn[cell0] = hreg0;
        hn[cell1] = hreg1;
        cn[cell0] = creg0;
        cn[cell1] = creg1;
    }
}

// ---------------------------------------------------------------- launch ----
extern "C" void kernel_launch(void* const* d_in, const int* in_sizes, int n_in,
                              void* d_out, int out_size)
{
    const float* input       = (const float*)d_in[0];
    const int*   batch_sizes = (const int*)  d_in[1];
    const float* h0          = (const float*)d_in[2];
    const float* c0          = (const float*)d_in[3];
    const float* W_ih        = (const float*)d_in[4];
    const float* W_hh        = (const float*)d_in[5];
    const float* b_ih        = (const float*)d_in[6];
    const float* b_hh        = (const float*)d_in[7];
    float* out = (float*)d_out;

    int T     = in_sizes[1];
    int total = in_sizes[0] / 256;
    if (total > TOTAL_MAX) total = TOTAL_MAX;
    if (T > TMAX) T = TMAX;

    const int GEMM_SMEM = 2 * (2 * 128 * AK) * 2;                     // 73728 B
    const int REC_SMEM  = 512 * KS * 2 + 2 * 8 * KS * 2 + TMAX * 4;   // 147712 B
    cudaFuncSetAttribute(gemm_hmma, cudaFuncAttributeMaxDynamicSharedMemorySize, GEMM_SMEM);
    cudaFuncSetAttribute(rec_kernel, cudaFuncAttributeMaxDynamicSharedMemorySize, REC_SMEM);

    setup_kernel<<<1, 1024>>>(batch_sizes, T);

    // fp16 prepass (single launch)
    __half* dA16;   cudaGetSymbolAddress((void**)&dA16, g_A16);
    __half* dW16;   cudaGetSymbolAddress((void**)&dW16, g_W16);
    __half* dOut1h; cudaGetSymbolAddress((void**)&dOut1h, g_out1h);
    {
        int n4a = in_sizes[0] / 4;
        int n4w = in_sizes[4] / 4;
        int n4  = n4a + n4w;
        cvt_kernel<<<(n4 + 255) / 256, 256>>>(input, dA16, n4a, W_ih, dW16, n4w);
    }

    dim3 ggrid((total + 127) / 128, 8);
    // layer 0
    gemm_hmma<<<ggrid, 256, GEMM_SMEM>>>(dA16, b_ih, b_hh, total, 0);
    rec_kernel<<<128, 256, REC_SMEM>>>(W_hh, h0, c0, out, total, T, 0);
    // layer 1
    gemm_hmma<<<ggrid, 256, GEMM_SMEM>>>(dOut1h, b_ih, b_hh, total, 1);
    rec_kernel<<<128, 256, REC_SMEM>>>(W_hh, h0, c0, out, total, T, 1);
}